// round 4
// baseline (speedup 1.0000x reference)
#include <cuda_runtime.h>
#include <cuda_bf16.h>

#define N_NODES 50000
#define N_EDGES 800000
#define NE_TOT  (N_EDGES + N_NODES)   // 850000
#define IN_CH   128
#define OUT_CH  128
#define HEADS   4
#define HEAD_DIM 32
#define NEG_SLOPE 0.2f
#define LN_EPS 1e-5f

#define SCAN_B 512
#define NTILES ((N_NODES + SCAN_B - 1) / SCAN_B)   // 98

// ---------------- scratch ---------------------------------------------------------
__device__ float g_xl[N_NODES * OUT_CH];
__device__ float g_xr[N_NODES * OUT_CH];
__device__ int   g_cnt[N_NODES];
__device__ int   g_fill[N_NODES];
__device__ int   g_rowptr[N_NODES + 1];
__device__ int   g_tilesum[NTILES];
__device__ int   g_tilebase[NTILES];
__device__ int   g_csr[NE_TOT];

__device__ __forceinline__ float lrelu(float f) {
    return f > 0.f ? f : NEG_SLOPE * f;
}

// ---- packed f32x2 helpers --------------------------------------------------------
typedef unsigned long long ull;
__device__ __forceinline__ ull pack2dup(float v) {
    ull r; asm("mov.b64 %0, {%1, %1};" : "=l"(r) : "f"(v)); return r;
}
__device__ __forceinline__ ull pack2(float lo, float hi) {
    ull r; asm("mov.b64 %0, {%1, %2};" : "=l"(r) : "f"(lo), "f"(hi)); return r;
}
__device__ __forceinline__ void fma2(ull& d, ull a, ull b) {
    asm("fma.rn.f32x2 %0, %1, %2, %0;" : "+l"(d) : "l"(a), "l"(b));
}
__device__ __forceinline__ float2 unpack2(ull v) {
    float2 f; asm("mov.b64 {%0, %1}, %2;" : "=f"(f.x), "=f"(f.y) : "l"(v)); return f;
}

// ---------------- kernel 0: init counters ----------------------------------------
__global__ void k_init() {
    int i = blockIdx.x * blockDim.x + threadIdx.x;
    if (i < N_NODES) {
        g_cnt[i] = 1;      // self loop pre-counted
        g_fill[i] = 0;
    }
}

// ---------------- kernel 1: dual GEMM, register-tiled 8x4x2 -----------------------
// block (32,8)=256 threads; 64 nodes/block; thread: 8 nodes x 4 channels x 2 mats
#define GN 64
__global__ __launch_bounds__(256) void k_gemm_dual(
    const float* __restrict__ x,
    const float* __restrict__ Wl, const float* __restrict__ bl,
    const float* __restrict__ Wr, const float* __restrict__ br)
{
    __shared__ float xs[GN][IN_CH];     // 32 KB
    int tx = threadIdx.x;               // 0..31 -> channels [4tx, 4tx+4)
    int ty = threadIdx.y;               // 0..7  -> node rows ty + 8r
    int tid = ty * 32 + tx;
    int n0 = blockIdx.x * GN;
    int c0 = tx * 4;

    // load x tile: 2048 float4, 256 threads -> 8 each, coalesced
    #pragma unroll
    for (int i = 0; i < 8; i++) {
        int idx = tid + i * 256;          // float4 index
        int r = idx >> 5, c = idx & 31;   // 32 float4 per row
        int n = n0 + r;
        float4 v = make_float4(0.f, 0.f, 0.f, 0.f);
        if (n < N_NODES) v = *reinterpret_cast<const float4*>(x + (size_t)n * IN_CH + c * 4);
        *reinterpret_cast<float4*>(&xs[r][c * 4]) = v;
    }
    __syncthreads();

    // accumulators: [row r][pair p] for each matrix; pair p covers channels c0+2p..c0+2p+1
    ull accl[8][2], accr[8][2];
    #pragma unroll
    for (int r = 0; r < 8; r++) {
        accl[r][0] = 0ull; accl[r][1] = 0ull;
        accr[r][0] = 0ull; accr[r][1] = 0ull;
    }

    #pragma unroll 2
    for (int k = 0; k < IN_CH; k++) {
        float4 wl4 = *reinterpret_cast<const float4*>(Wl + (size_t)k * OUT_CH + c0);  // LDG.128
        float4 wr4 = *reinterpret_cast<const float4*>(Wr + (size_t)k * OUT_CH + c0);  // LDG.128
        ull wl0 = pack2(wl4.x, wl4.y), wl1 = pack2(wl4.z, wl4.w);
        ull wr0 = pack2(wr4.x, wr4.y), wr1 = pack2(wr4.z, wr4.w);
        #pragma unroll
        for (int r = 0; r < 8; r++) {
            ull x2 = pack2dup(xs[ty + r * 8][k]);   // broadcast LDS.32
            fma2(accl[r][0], x2, wl0);
            fma2(accl[r][1], x2, wl1);
            fma2(accr[r][0], x2, wr0);
            fma2(accr[r][1], x2, wr1);
        }
    }

    float4 b_l = *reinterpret_cast<const float4*>(bl + c0);
    float4 b_r = *reinterpret_cast<const float4*>(br + c0);
    #pragma unroll
    for (int r = 0; r < 8; r++) {
        int n = n0 + ty + r * 8;
        if (n < N_NODES) {
            float2 l0 = unpack2(accl[r][0]), l1 = unpack2(accl[r][1]);
            float2 r0 = unpack2(accr[r][0]), r1 = unpack2(accr[r][1]);
            float4 vl = make_float4(l0.x + b_l.x, l0.y + b_l.y, l1.x + b_l.z, l1.y + b_l.w);
            float4 vr = make_float4(r0.x + b_r.x, r0.y + b_r.y, r1.x + b_r.z, r1.y + b_r.w);
            *reinterpret_cast<float4*>(g_xl + (size_t)n * OUT_CH + c0) = vl;
            *reinterpret_cast<float4*>(g_xr + (size_t)n * OUT_CH + c0) = vr;
        }
    }
}

// ---------------- kernel 2: histogram of destination degrees ----------------------
__global__ __launch_bounds__(256) void k_hist(const int* __restrict__ ei) {
    int e = blockIdx.x * blockDim.x + threadIdx.x;
    if (e < N_EDGES) atomicAdd(&g_cnt[ei[N_EDGES + e]], 1);
}

// ---------------- scan chain -------------------------------------------------------
__global__ __launch_bounds__(SCAN_B) void k_scan1() {
    __shared__ int sh[SCAN_B];
    int t = blockIdx.x, tid = threadIdx.x;
    int i = t * SCAN_B + tid;
    int v = (i < N_NODES) ? g_cnt[i] : 0;
    sh[tid] = v;
    __syncthreads();
    #pragma unroll
    for (int off = 1; off < SCAN_B; off <<= 1) {
        int add = (tid >= off) ? sh[tid - off] : 0;
        __syncthreads();
        sh[tid] += add;
        __syncthreads();
    }
    if (i < N_NODES) g_rowptr[i] = sh[tid] - v;
    if (tid == SCAN_B - 1) g_tilesum[t] = sh[tid];
}

__global__ __launch_bounds__(128) void k_scan2() {
    int t = threadIdx.x;
    int lane = t & 31, w = t >> 5;
    int v = (t < NTILES) ? g_tilesum[t] : 0;
    int inc = v;
    #pragma unroll
    for (int off = 1; off < 32; off <<= 1) {
        int n = __shfl_up_sync(0xFFFFFFFFu, inc, off);
        if (lane >= off) inc += n;
    }
    __shared__ int wsum[4];
    if (lane == 31) wsum[w] = inc;
    __syncthreads();
    int prefix = 0;
    #pragma unroll
    for (int j = 0; j < 4; j++) if (j < w) prefix += wsum[j];
    inc += prefix;
    if (t < NTILES) g_tilebase[t] = inc - v;
    if (t == NTILES - 1) g_rowptr[N_NODES] = inc;
}

__global__ __launch_bounds__(SCAN_B) void k_scan3() {
    int i = blockIdx.x * SCAN_B + threadIdx.x;
    if (i < N_NODES) g_rowptr[i] += g_tilebase[blockIdx.x];
}

// ---------------- kernel 4: fill CSR ----------------------------------------------
__global__ __launch_bounds__(256) void k_fill(const int* __restrict__ ei) {
    int t = blockIdx.x * blockDim.x + threadIdx.x;
    if (t >= NE_TOT) return;
    int src, dst;
    if (t < N_EDGES) { src = ei[t]; dst = ei[N_EDGES + t]; }
    else             { src = dst = t - N_EDGES; }
    int pos = g_rowptr[dst] + atomicAdd(&g_fill[dst], 1);
    g_csr[pos] = src;
}

// ---------------- kernel 5: fused attention aggregate + SiLU + LayerNorm ----------
// one warp per node, software-pipelined gather
__global__ __launch_bounds__(256) void k_aggregate(
    const float* __restrict__ att,
    const float* __restrict__ bias,
    const float* __restrict__ gamma,
    const float* __restrict__ beta,
    float* __restrict__ out)
{
    int warp = (blockIdx.x * blockDim.x + threadIdx.x) >> 5;
    int lane = threadIdx.x & 31;
    if (warp >= N_NODES) return;

    float4 a   = *reinterpret_cast<const float4*>(att + lane * 4);
    float4 xr4 = *reinterpret_cast<const float4*>(g_xr + (size_t)warp * OUT_CH + lane * 4);

    int base = g_rowptr[warp];
    int end  = g_rowptr[warp + 1];

    float4 acc = make_float4(0.f, 0.f, 0.f, 0.f);
    float denom = 0.f;

    // pipelined: prefetch next src row while reducing current one
    int src = g_csr[base];
    float4 vl = *reinterpret_cast<const float4*>(g_xl + (size_t)src * OUT_CH + lane * 4);

    for (int k = base; k < end; k++) {
        float4 cur = vl;
        if (k + 1 < end) {
            int nsrc = g_csr[k + 1];
            vl = *reinterpret_cast<const float4*>(g_xl + (size_t)nsrc * OUT_CH + lane * 4);
        }

        float s = a.x * lrelu(cur.x + xr4.x)
                + a.y * lrelu(cur.y + xr4.y)
                + a.z * lrelu(cur.z + xr4.z)
                + a.w * lrelu(cur.w + xr4.w);
        s += __shfl_xor_sync(0xFFFFFFFFu, s, 1);
        s += __shfl_xor_sync(0xFFFFFFFFu, s, 2);
        s += __shfl_xor_sync(0xFFFFFFFFu, s, 4);

        float w = __expf(s);
        denom += w;
        acc.x = fmaf(w, cur.x, acc.x);
        acc.y = fmaf(w, cur.y, acc.y);
        acc.z = fmaf(w, cur.z, acc.z);
        acc.w = fmaf(w, cur.w, acc.w);
    }

    float inv = __frcp_rn(denom);
    float4 b = *reinterpret_cast<const float4*>(bias + lane * 4);
    float4 v;
    v.x = fmaf(acc.x, inv, b.x);
    v.y = fmaf(acc.y, inv, b.y);
    v.z = fmaf(acc.z, inv, b.z);
    v.w = fmaf(acc.w, inv, b.w);

    v.x = v.x / (1.f + __expf(-v.x));
    v.y = v.y / (1.f + __expf(-v.y));
    v.z = v.z / (1.f + __expf(-v.z));
    v.w = v.w / (1.f + __expf(-v.w));

    float sum = v.x + v.y + v.z + v.w;
    float sq  = v.x * v.x + v.y * v.y + v.z * v.z + v.w * v.w;
    #pragma unroll
    for (int off = 16; off; off >>= 1) {
        sum += __shfl_xor_sync(0xFFFFFFFFu, sum, off);
        sq  += __shfl_xor_sync(0xFFFFFFFFu, sq,  off);
    }
    float mu   = sum * (1.f / OUT_CH);
    float var  = sq * (1.f / OUT_CH) - mu * mu;
    float rstd = rsqrtf(var + LN_EPS);

    float4 g  = *reinterpret_cast<const float4*>(gamma + lane * 4);
    float4 be = *reinterpret_cast<const float4*>(beta  + lane * 4);
    float4 r;
    r.x = (v.x - mu) * rstd * g.x + be.x;
    r.y = (v.y - mu) * rstd * g.y + be.y;
    r.z = (v.z - mu) * rstd * g.z + be.z;
    r.w = (v.w - mu) * rstd * g.w + be.w;
    *reinterpret_cast<float4*>(out + (size_t)warp * OUT_CH + lane * 4) = r;
}

// ---------------- launcher ----------------------------------------------------------
extern "C" void kernel_launch(void* const* d_in, const int* in_sizes, int n_in,
                              void* d_out, int out_size)
{
    const float* x    = (const float*)d_in[0];
    const int*   ei   = (const int*)  d_in[1];
    const float* Wl   = (const float*)d_in[2];
    const float* bl   = (const float*)d_in[3];
    const float* Wr   = (const float*)d_in[4];
    const float* br   = (const float*)d_in[5];
    const float* att  = (const float*)d_in[6];
    const float* bias = (const float*)d_in[7];
    const float* gam  = (const float*)d_in[8];
    const float* bet  = (const float*)d_in[9];
    float* out = (float*)d_out;

    k_init<<<(N_NODES + 255) / 256, 256>>>();

    k_gemm_dual<<<(N_NODES + GN - 1) / GN, dim3(32, 8)>>>(x, Wl, bl, Wr, br);

    k_hist<<<(N_EDGES + 255) / 256, 256>>>(ei);

    k_scan1<<<NTILES, SCAN_B>>>();
    k_scan2<<<1, 128>>>();
    k_scan3<<<NTILES, SCAN_B>>>();

    k_fill<<<(NE_TOT + 255) / 256, 256>>>(ei);

    k_aggregate<<<(N_NODES * 32 + 255) / 256, 256>>>(att, bias, gam, bet, out);
}

// round 5
// speedup vs baseline: 1.0417x; 1.0417x over previous
#include <cuda_runtime.h>
#include <cuda_bf16.h>

#define N_NODES 50000
#define N_EDGES 800000
#define NE_TOT  (N_EDGES + N_NODES)   // 850000
#define IN_CH   128
#define OUT_CH  128
#define HEADS   4
#define HEAD_DIM 32
#define NEG_SLOPE 0.2f
#define LN_EPS 1e-5f

#define SCAN_B 512
#define NTILES ((N_NODES + SCAN_B - 1) / SCAN_B)   // 98

// ---------------- scratch ---------------------------------------------------------
__device__ float g_xl[N_NODES * OUT_CH];
__device__ float g_xr[N_NODES * OUT_CH];
__device__ int   g_cnt[N_NODES];
__device__ int   g_fill[N_NODES];
__device__ int   g_rowptr[N_NODES + 1];
__device__ int   g_csr[NE_TOT];
// decoupled-lookback scan state
__device__ int   g_scan_agg[NTILES];
__device__ int   g_scan_pref[NTILES];
__device__ volatile int g_scan_flag[NTILES];   // 0=invalid, 1=agg ready, 2=prefix ready

__device__ __forceinline__ float lrelu(float f) {
    return f > 0.f ? f : NEG_SLOPE * f;
}

// ---- packed f32x2 helpers ----------------------------------------------------------
typedef unsigned long long ull;
__device__ __forceinline__ ull pack2(float lo, float hi) {
    ull r; asm("mov.b64 %0, {%1, %2};" : "=l"(r) : "f"(lo), "f"(hi)); return r;
}
__device__ __forceinline__ ull pack2dup(float v) {
    ull r; asm("mov.b64 %0, {%1, %1};" : "=l"(r) : "f"(v)); return r;
}
__device__ __forceinline__ void fma2(ull& d, ull a, ull b) {
    asm("fma.rn.f32x2 %0, %1, %2, %0;" : "+l"(d) : "l"(a), "l"(b));
}
__device__ __forceinline__ float2 unpack2(ull v) {
    float2 f; asm("mov.b64 {%0, %1}, %2;" : "=f"(f.x), "=f"(f.y) : "l"(v)); return f;
}

// ---------------- kernel 0: init counters + scan flags ------------------------------
__global__ void k_init() {
    int i = blockIdx.x * blockDim.x + threadIdx.x;
    if (i < N_NODES) {
        g_cnt[i] = 1;      // self loop pre-counted
        g_fill[i] = 0;
    }
    if (i < NTILES) {
        g_scan_flag[i] = 0;
    }
}

// ---------------- kernel 1: histogram of destination degrees ------------------------
__global__ __launch_bounds__(256) void k_hist(const int* __restrict__ ei) {
    int e = blockIdx.x * blockDim.x + threadIdx.x;
    if (e < N_EDGES) atomicAdd(&g_cnt[ei[N_EDGES + e]], 1);
}

// ---------------- kernel 2: single-pass exclusive scan (decoupled lookback) ---------
__global__ __launch_bounds__(SCAN_B) void k_scan() {
    __shared__ int warp_excl[16];     // exclusive prefix of each warp's total
    __shared__ int s_total;
    __shared__ int s_prev;

    int t = blockIdx.x, tid = threadIdx.x;
    int i = t * SCAN_B + tid;
    int lane = tid & 31, w = tid >> 5;

    int v = (i < N_NODES) ? g_cnt[i] : 0;

    // warp inclusive scan
    int inc = v;
    #pragma unroll
    for (int off = 1; off < 32; off <<= 1) {
        int n = __shfl_up_sync(0xFFFFFFFFu, inc, off);
        if (lane >= off) inc += n;
    }
    if (lane == 31) warp_excl[w] = inc;   // warp totals (temporarily)
    __syncthreads();

    if (w == 0) {
        int ws = (lane < 16) ? warp_excl[lane] : 0;
        int wi = ws;
        #pragma unroll
        for (int off = 1; off < 16; off <<= 1) {
            int n = __shfl_up_sync(0xFFFFFFFFu, wi, off);
            if (lane >= off) wi += n;
        }
        if (lane < 16) warp_excl[lane] = wi - ws;   // exclusive warp prefix
        if (lane == 15) s_total = wi;               // block total
    }
    __syncthreads();

    int block_total = s_total;
    int excl_in_block = warp_excl[w] + inc - v;

    // publish aggregate, then lookback (thread 0)
    if (tid == 0) {
        if (t == 0) {
            g_scan_pref[0] = block_total;
            __threadfence();
            g_scan_flag[0] = 2;
            s_prev = 0;
        } else {
            g_scan_agg[t] = block_total;
            __threadfence();
            g_scan_flag[t] = 1;
            int run = 0;
            int p = t - 1;
            while (true) {
                int f;
                do { f = g_scan_flag[p]; } while (f == 0);
                __threadfence();
                if (f == 2) { run += g_scan_pref[p]; break; }
                run += g_scan_agg[p];
                p--;
            }
            g_scan_pref[t] = run + block_total;
            __threadfence();
            g_scan_flag[t] = 2;
            s_prev = run;
        }
    }
    __syncthreads();

    if (i < N_NODES) g_rowptr[i] = s_prev + excl_in_block;
    if (i == N_NODES - 1) g_rowptr[N_NODES] = s_prev + block_total;
}

// ---------------- kernel 3: dual GEMM (R3 best config: f32x2, (64,4) block) ---------
#define GN 32
__global__ __launch_bounds__(256) void k_gemm_dual(
    const float* __restrict__ x,
    const float* __restrict__ Wl, const float* __restrict__ bl,
    const float* __restrict__ Wr, const float* __restrict__ br)
{
    __shared__ float xs[GN][IN_CH];
    int tx = threadIdx.x;            // 0..63
    int ty = threadIdx.y;            // 0..3
    int tid = ty * 64 + tx;
    int n0 = blockIdx.x * GN;
    int c0 = tx * 2;

    #pragma unroll
    for (int i = 0; i < 4; i++) {
        int idx = tid + i * 256;
        int r = idx >> 5, c = idx & 31;
        int n = n0 + r;
        float4 v = make_float4(0.f, 0.f, 0.f, 0.f);
        if (n < N_NODES) v = *reinterpret_cast<const float4*>(x + (size_t)n * IN_CH + c * 4);
        *reinterpret_cast<float4*>(&xs[r][c * 4]) = v;
    }
    __syncthreads();

    ull accl[8], accr[8];
    #pragma unroll
    for (int r = 0; r < 8; r++) { accl[r] = 0ull; accr[r] = 0ull; }

    #pragma unroll 2
    for (int k = 0; k < IN_CH; k += 2) {
        ull wl0 = *reinterpret_cast<const ull*>(Wl + (size_t)k * OUT_CH + c0);
        ull wl1 = *reinterpret_cast<const ull*>(Wl + (size_t)(k + 1) * OUT_CH + c0);
        ull wr0 = *reinterpret_cast<const ull*>(Wr + (size_t)k * OUT_CH + c0);
        ull wr1 = *reinterpret_cast<const ull*>(Wr + (size_t)(k + 1) * OUT_CH + c0);
        #pragma unroll
        for (int r = 0; r < 8; r++) {
            float2 xv = *reinterpret_cast<const float2*>(&xs[ty + r * 4][k]);
            ull x0 = pack2dup(xv.x);
            ull x1 = pack2dup(xv.y);
            fma2(accl[r], x0, wl0);
            fma2(accl[r], x1, wl1);
            fma2(accr[r], x0, wr0);
            fma2(accr[r], x1, wr1);
        }
    }

    float2 b_l = *reinterpret_cast<const float2*>(bl + c0);
    float2 b_r = *reinterpret_cast<const float2*>(br + c0);
    #pragma unroll
    for (int r = 0; r < 8; r++) {
        int n = n0 + ty + r * 4;
        if (n < N_NODES) {
            float2 vl = unpack2(accl[r]);
            float2 vr = unpack2(accr[r]);
            vl.x += b_l.x; vl.y += b_l.y;
            vr.x += b_r.x; vr.y += b_r.y;
            *reinterpret_cast<float2*>(g_xl + (size_t)n * OUT_CH + c0) = vl;
            *reinterpret_cast<float2*>(g_xr + (size_t)n * OUT_CH + c0) = vr;
        }
    }
}

// ---------------- kernel 4: fill CSR -------------------------------------------------
__global__ __launch_bounds__(256) void k_fill(const int* __restrict__ ei) {
    int t = blockIdx.x * blockDim.x + threadIdx.x;
    if (t >= NE_TOT) return;
    int src, dst;
    if (t < N_EDGES) { src = ei[t]; dst = ei[N_EDGES + t]; }
    else             { src = dst = t - N_EDGES; }
    int pos = g_rowptr[dst] + atomicAdd(&g_fill[dst], 1);
    g_csr[pos] = src;
}

// ---------------- kernel 5: fused aggregate + SiLU + LayerNorm (2-edge unroll) ------
__global__ __launch_bounds__(256) void k_aggregate(
    const float* __restrict__ att,
    const float* __restrict__ bias,
    const float* __restrict__ gamma,
    const float* __restrict__ beta,
    float* __restrict__ out)
{
    int warp = (blockIdx.x * blockDim.x + threadIdx.x) >> 5;
    int lane = threadIdx.x & 31;
    if (warp >= N_NODES) return;

    float4 a   = *reinterpret_cast<const float4*>(att + lane * 4);
    float4 xr4 = *reinterpret_cast<const float4*>(g_xr + (size_t)warp * OUT_CH + lane * 4);

    int base = g_rowptr[warp];
    int end  = g_rowptr[warp + 1];

    float4 acc = make_float4(0.f, 0.f, 0.f, 0.f);
    float denom = 0.f;

    int k = base;
    for (; k + 1 < end; k += 2) {
        int s0 = g_csr[k];
        int s1 = g_csr[k + 1];
        float4 v0 = *reinterpret_cast<const float4*>(g_xl + (size_t)s0 * OUT_CH + lane * 4);
        float4 v1 = *reinterpret_cast<const float4*>(g_xl + (size_t)s1 * OUT_CH + lane * 4);

        float sc0 = a.x * lrelu(v0.x + xr4.x) + a.y * lrelu(v0.y + xr4.y)
                  + a.z * lrelu(v0.z + xr4.z) + a.w * lrelu(v0.w + xr4.w);
        float sc1 = a.x * lrelu(v1.x + xr4.x) + a.y * lrelu(v1.y + xr4.y)
                  + a.z * lrelu(v1.z + xr4.z) + a.w * lrelu(v1.w + xr4.w);

        sc0 += __shfl_xor_sync(0xFFFFFFFFu, sc0, 1);
        sc1 += __shfl_xor_sync(0xFFFFFFFFu, sc1, 1);
        sc0 += __shfl_xor_sync(0xFFFFFFFFu, sc0, 2);
        sc1 += __shfl_xor_sync(0xFFFFFFFFu, sc1, 2);
        sc0 += __shfl_xor_sync(0xFFFFFFFFu, sc0, 4);
        sc1 += __shfl_xor_sync(0xFFFFFFFFu, sc1, 4);

        float w0 = __expf(sc0);
        float w1 = __expf(sc1);
        denom += w0 + w1;
        acc.x = fmaf(w0, v0.x, fmaf(w1, v1.x, acc.x));
        acc.y = fmaf(w0, v0.y, fmaf(w1, v1.y, acc.y));
        acc.z = fmaf(w0, v0.z, fmaf(w1, v1.z, acc.z));
        acc.w = fmaf(w0, v0.w, fmaf(w1, v1.w, acc.w));
    }
    if (k < end) {
        int s0 = g_csr[k];
        float4 v0 = *reinterpret_cast<const float4*>(g_xl + (size_t)s0 * OUT_CH + lane * 4);
        float sc0 = a.x * lrelu(v0.x + xr4.x) + a.y * lrelu(v0.y + xr4.y)
                  + a.z * lrelu(v0.z + xr4.z) + a.w * lrelu(v0.w + xr4.w);
        sc0 += __shfl_xor_sync(0xFFFFFFFFu, sc0, 1);
        sc0 += __shfl_xor_sync(0xFFFFFFFFu, sc0, 2);
        sc0 += __shfl_xor_sync(0xFFFFFFFFu, sc0, 4);
        float w0 = __expf(sc0);
        denom += w0;
        acc.x = fmaf(w0, v0.x, acc.x);
        acc.y = fmaf(w0, v0.y, acc.y);
        acc.z = fmaf(w0, v0.z, acc.z);
        acc.w = fmaf(w0, v0.w, acc.w);
    }

    float inv = __frcp_rn(denom);
    float4 b = *reinterpret_cast<const float4*>(bias + lane * 4);
    float4 v;
    v.x = fmaf(acc.x, inv, b.x);
    v.y = fmaf(acc.y, inv, b.y);
    v.z = fmaf(acc.z, inv, b.z);
    v.w = fmaf(acc.w, inv, b.w);

    v.x = v.x / (1.f + __expf(-v.x));
    v.y = v.y / (1.f + __expf(-v.y));
    v.z = v.z / (1.f + __expf(-v.z));
    v.w = v.w / (1.f + __expf(-v.w));

    float sum = v.x + v.y + v.z + v.w;
    float sq  = v.x * v.x + v.y * v.y + v.z * v.z + v.w * v.w;
    #pragma unroll
    for (int off = 16; off; off >>= 1) {
        sum += __shfl_xor_sync(0xFFFFFFFFu, sum, off);
        sq  += __shfl_xor_sync(0xFFFFFFFFu, sq,  off);
    }
    float mu   = sum * (1.f / OUT_CH);
    float var  = sq * (1.f / OUT_CH) - mu * mu;
    float rstd = rsqrtf(var + LN_EPS);

    float4 g  = *reinterpret_cast<const float4*>(gamma + lane * 4);
    float4 be = *reinterpret_cast<const float4*>(beta  + lane * 4);
    float4 r;
    r.x = (v.x - mu) * rstd * g.x + be.x;
    r.y = (v.y - mu) * rstd * g.y + be.y;
    r.z = (v.z - mu) * rstd * g.z + be.z;
    r.w = (v.w - mu) * rstd * g.w + be.w;
    *reinterpret_cast<float4*>(out + (size_t)warp * OUT_CH + lane * 4) = r;
}

// ---------------- launcher ------------------------------------------------------------
extern "C" void kernel_launch(void* const* d_in, const int* in_sizes, int n_in,
                              void* d_out, int out_size)
{
    const float* x    = (const float*)d_in[0];
    const int*   ei   = (const int*)  d_in[1];
    const float* Wl   = (const float*)d_in[2];
    const float* bl   = (const float*)d_in[3];
    const float* Wr   = (const float*)d_in[4];
    const float* br   = (const float*)d_in[5];
    const float* att  = (const float*)d_in[6];
    const float* bias = (const float*)d_in[7];
    const float* gam  = (const float*)d_in[8];
    const float* bet  = (const float*)d_in[9];
    float* out = (float*)d_out;

    // order chosen so k_gemm_dual sits at iteration-launch index 3 (ncu capture slot)
    k_init<<<(N_NODES + 255) / 256, 256>>>();                       // 0
    k_hist<<<(N_EDGES + 255) / 256, 256>>>(ei);                     // 1
    k_scan<<<NTILES, SCAN_B>>>();                                   // 2
    k_gemm_dual<<<(N_NODES + GN - 1) / GN, dim3(64, 4)>>>(x, Wl, bl, Wr, br);  // 3
    k_fill<<<(NE_TOT + 255) / 256, 256>>>(ei);                      // 4
    k_aggregate<<<(N_NODES * 32 + 255) / 256, 256>>>(att, bias, gam, bet, out); // 5
}

// round 6
// speedup vs baseline: 1.1929x; 1.1451x over previous
#include <cuda_runtime.h>
#include <cuda_bf16.h>
#include <cstdint>

#define N_NODES 50000
#define N_EDGES 800000
#define NE_TOT  (N_EDGES + N_NODES)   // 850000
#define IN_CH   128
#define OUT_CH  128
#define HEADS   4
#define HEAD_DIM 32
#define NEG_SLOPE 0.2f
#define LN_EPS 1e-5f

#define SCAN_B 512
#define NTILES ((N_NODES + SCAN_B - 1) / SCAN_B)   // 98

// ---------------- scratch ---------------------------------------------------------
__device__ float    g_xl[N_NODES * OUT_CH];
__device__ float    g_xr[N_NODES * OUT_CH];
__device__ uint32_t g_wl32[IN_CH * OUT_CH];    // Wl in tf32 bit format
__device__ uint32_t g_wr32[IN_CH * OUT_CH];    // Wr in tf32 bit format
__device__ int      g_cnt[N_NODES];
__device__ int      g_fill[N_NODES];
__device__ int      g_rowptr[N_NODES + 1];
__device__ int      g_csr[NE_TOT];
// decoupled-lookback scan state
__device__ int      g_scan_agg[NTILES];
__device__ int      g_scan_pref[NTILES];
__device__ volatile int g_scan_flag[NTILES];

__device__ __forceinline__ float lrelu(float f) {
    return f > 0.f ? f : NEG_SLOPE * f;
}

__device__ __forceinline__ uint32_t f2tf32(float v) {
    uint32_t r;
    asm("cvt.rna.tf32.f32 %0, %1;" : "=r"(r) : "f"(v));
    return r;
}

// ---------------- kernel A: convert W to tf32 ---------------------------------------
__global__ void k_wconv(const float* __restrict__ Wl, const float* __restrict__ Wr) {
    int i = blockIdx.x * blockDim.x + threadIdx.x;
    if (i < IN_CH * OUT_CH) {
        g_wl32[i] = f2tf32(Wl[i]);
        g_wr32[i] = f2tf32(Wr[i]);
    }
}

// ---------------- kernel 0: init counters + scan flags ------------------------------
__global__ void k_init() {
    int i = blockIdx.x * blockDim.x + threadIdx.x;
    if (i < N_NODES) {
        g_cnt[i] = 1;      // self loop pre-counted
        g_fill[i] = 0;
    }
    if (i < NTILES) {
        g_scan_flag[i] = 0;
    }
}

// ---------------- kernel 1: histogram of destination degrees ------------------------
__global__ __launch_bounds__(256) void k_hist(const int* __restrict__ ei) {
    int e = blockIdx.x * blockDim.x + threadIdx.x;
    if (e < N_EDGES) atomicAdd(&g_cnt[ei[N_EDGES + e]], 1);
}

// ---------------- kernel 2: dual GEMM via mma.sync tf32 -----------------------------
// block 512 threads = 16 warps; 64 nodes/block.
// warp w: matrix = w>>3 (0:Wl 1:Wr), m16-tile = (w>>1)&3, n-half = w&1 (64 channels)
// per warp: 16 nodes x 64 channels, k-loop 16 steps of m16n8k8
#define XS_PITCH 132    // 128 + 4 pad: conflict-free A-fragment LDS
__global__ __launch_bounds__(512, 2) void k_gemm_mma(
    const float* __restrict__ x,
    const float* __restrict__ bl,
    const float* __restrict__ br)
{
    __shared__ uint32_t xs[64 * XS_PITCH];    // x tile in tf32 bits, padded

    int tid = threadIdx.x;
    int nblk = blockIdx.x * 64;

    // load + convert x tile (64 rows x 128 cols), coalesced float4
    #pragma unroll
    for (int i = 0; i < 4; i++) {
        int idx = tid + i * 512;              // float4 index, 2048 total
        int r = idx >> 5, c = idx & 31;       // 32 float4 per row
        int n = nblk + r;
        float4 v = make_float4(0.f, 0.f, 0.f, 0.f);
        if (n < N_NODES) v = *reinterpret_cast<const float4*>(x + (size_t)n * IN_CH + c * 4);
        uint32_t* p = &xs[r * XS_PITCH + c * 4];
        uint4 t;
        t.x = f2tf32(v.x); t.y = f2tf32(v.y); t.z = f2tf32(v.z); t.w = f2tf32(v.w);
        *reinterpret_cast<uint4*>(p) = t;     // 16B aligned: XS_PITCH%4==0
    }
    __syncthreads();

    int wid  = tid >> 5;
    int lane = tid & 31;
    int gid  = lane >> 2;      // 0..7
    int tig  = lane & 3;       // 0..3
    int mat  = wid >> 3;       // 0: Wl, 1: Wr
    int mt   = (wid >> 1) & 3; // m16 tile within block
    int nh   = wid & 1;        // n half (64 channels)

    const uint32_t* W = mat ? g_wr32 : g_wl32;

    float acc[8][4];
    #pragma unroll
    for (int nt = 0; nt < 8; nt++)
        #pragma unroll
        for (int j = 0; j < 4; j++) acc[nt][j] = 0.f;

    int arow0 = (mt * 16 + gid) * XS_PITCH;
    int arow1 = arow0 + 8 * XS_PITCH;
    int nbase = nh * 64;

    #pragma unroll
    for (int ks = 0; ks < 16; ks++) {
        int k0 = ks * 8;
        uint32_t a0 = xs[arow0 + k0 + tig];
        uint32_t a1 = xs[arow1 + k0 + tig];
        uint32_t a2 = xs[arow0 + k0 + tig + 4];
        uint32_t a3 = xs[arow1 + k0 + tig + 4];

        #pragma unroll
        for (int nt = 0; nt < 8; nt++) {
            int n0 = nbase + nt * 8;
            uint32_t b0 = W[(k0 + tig) * OUT_CH + n0 + gid];
            uint32_t b1 = W[(k0 + tig + 4) * OUT_CH + n0 + gid];
            asm volatile(
                "mma.sync.aligned.m16n8k8.row.col.f32.tf32.tf32.f32 "
                "{%0,%1,%2,%3}, {%4,%5,%6,%7}, {%8,%9}, {%0,%1,%2,%3};"
                : "+f"(acc[nt][0]), "+f"(acc[nt][1]), "+f"(acc[nt][2]), "+f"(acc[nt][3])
                : "r"(a0), "r"(a1), "r"(a2), "r"(a3), "r"(b0), "r"(b1));
        }
    }

    // epilogue: add bias, store float2 pairs
    const float* bv = mat ? br : bl;
    float* dst = mat ? g_xr : g_xl;
    int r0 = nblk + mt * 16 + gid;
    int r1 = r0 + 8;
    bool ok0 = (r0 < N_NODES), ok1 = (r1 < N_NODES);

    #pragma unroll
    for (int nt = 0; nt < 8; nt++) {
        int c = nbase + nt * 8 + 2 * tig;
        float2 b2 = *reinterpret_cast<const float2*>(bv + c);
        if (ok0) {
            float2 o = make_float2(acc[nt][0] + b2.x, acc[nt][1] + b2.y);
            *reinterpret_cast<float2*>(dst + (size_t)r0 * OUT_CH + c) = o;
        }
        if (ok1) {
            float2 o = make_float2(acc[nt][2] + b2.x, acc[nt][3] + b2.y);
            *reinterpret_cast<float2*>(dst + (size_t)r1 * OUT_CH + c) = o;
        }
    }
}

// ---------------- kernel 3: single-pass exclusive scan (decoupled lookback) ---------
__global__ __launch_bounds__(SCAN_B) void k_scan() {
    __shared__ int warp_excl[16];
    __shared__ int s_total;
    __shared__ int s_prev;

    int t = blockIdx.x, tid = threadIdx.x;
    int i = t * SCAN_B + tid;
    int lane = tid & 31, w = tid >> 5;

    int v = (i < N_NODES) ? g_cnt[i] : 0;

    int inc = v;
    #pragma unroll
    for (int off = 1; off < 32; off <<= 1) {
        int n = __shfl_up_sync(0xFFFFFFFFu, inc, off);
        if (lane >= off) inc += n;
    }
    if (lane == 31) warp_excl[w] = inc;
    __syncthreads();

    if (w == 0) {
        int ws = (lane < 16) ? warp_excl[lane] : 0;
        int wi = ws;
        #pragma unroll
        for (int off = 1; off < 16; off <<= 1) {
            int n = __shfl_up_sync(0xFFFFFFFFu, wi, off);
            if (lane >= off) wi += n;
        }
        if (lane < 16) warp_excl[lane] = wi - ws;
        if (lane == 15) s_total = wi;
    }
    __syncthreads();

    int block_total = s_total;
    int excl_in_block = warp_excl[w] + inc - v;

    if (tid == 0) {
        if (t == 0) {
            g_scan_pref[0] = block_total;
            __threadfence();
            g_scan_flag[0] = 2;
            s_prev = 0;
        } else {
            g_scan_agg[t] = block_total;
            __threadfence();
            g_scan_flag[t] = 1;
            int run = 0;
            int p = t - 1;
            while (true) {
                int f;
                do { f = g_scan_flag[p]; } while (f == 0);
                __threadfence();
                if (f == 2) { run += g_scan_pref[p]; break; }
                run += g_scan_agg[p];
                p--;
            }
            g_scan_pref[t] = run + block_total;
            __threadfence();
            g_scan_flag[t] = 2;
            s_prev = run;
        }
    }
    __syncthreads();

    if (i < N_NODES) g_rowptr[i] = s_prev + excl_in_block;
    if (i == N_NODES - 1) g_rowptr[N_NODES] = s_prev + block_total;
}

// ---------------- kernel 4: fill CSR -------------------------------------------------
__global__ __launch_bounds__(256) void k_fill(const int* __restrict__ ei) {
    int t = blockIdx.x * blockDim.x + threadIdx.x;
    if (t >= NE_TOT) return;
    int src, dst;
    if (t < N_EDGES) { src = ei[t]; dst = ei[N_EDGES + t]; }
    else             { src = dst = t - N_EDGES; }
    int pos = g_rowptr[dst] + atomicAdd(&g_fill[dst], 1);
    g_csr[pos] = src;
}

// ---------------- kernel 5: fused aggregate + SiLU + LayerNorm (2-edge unroll) ------
__global__ __launch_bounds__(256) void k_aggregate(
    const float* __restrict__ att,
    const float* __restrict__ bias,
    const float* __restrict__ gamma,
    const float* __restrict__ beta,
    float* __restrict__ out)
{
    int warp = (blockIdx.x * blockDim.x + threadIdx.x) >> 5;
    int lane = threadIdx.x & 31;
    if (warp >= N_NODES) return;

    float4 a   = *reinterpret_cast<const float4*>(att + lane * 4);
    float4 xr4 = *reinterpret_cast<const float4*>(g_xr + (size_t)warp * OUT_CH + lane * 4);

    int base = g_rowptr[warp];
    int end  = g_rowptr[warp + 1];

    float4 acc = make_float4(0.f, 0.f, 0.f, 0.f);
    float denom = 0.f;

    int k = base;
    for (; k + 1 < end; k += 2) {
        int s0 = g_csr[k];
        int s1 = g_csr[k + 1];
        float4 v0 = *reinterpret_cast<const float4*>(g_xl + (size_t)s0 * OUT_CH + lane * 4);
        float4 v1 = *reinterpret_cast<const float4*>(g_xl + (size_t)s1 * OUT_CH + lane * 4);

        float sc0 = a.x * lrelu(v0.x + xr4.x) + a.y * lrelu(v0.y + xr4.y)
                  + a.z * lrelu(v0.z + xr4.z) + a.w * lrelu(v0.w + xr4.w);
        float sc1 = a.x * lrelu(v1.x + xr4.x) + a.y * lrelu(v1.y + xr4.y)
                  + a.z * lrelu(v1.z + xr4.z) + a.w * lrelu(v1.w + xr4.w);

        sc0 += __shfl_xor_sync(0xFFFFFFFFu, sc0, 1);
        sc1 += __shfl_xor_sync(0xFFFFFFFFu, sc1, 1);
        sc0 += __shfl_xor_sync(0xFFFFFFFFu, sc0, 2);
        sc1 += __shfl_xor_sync(0xFFFFFFFFu, sc1, 2);
        sc0 += __shfl_xor_sync(0xFFFFFFFFu, sc0, 4);
        sc1 += __shfl_xor_sync(0xFFFFFFFFu, sc1, 4);

        float w0 = __expf(sc0);
        float w1 = __expf(sc1);
        denom += w0 + w1;
        acc.x = fmaf(w0, v0.x, fmaf(w1, v1.x, acc.x));
        acc.y = fmaf(w0, v0.y, fmaf(w1, v1.y, acc.y));
        acc.z = fmaf(w0, v0.z, fmaf(w1, v1.z, acc.z));
        acc.w = fmaf(w0, v0.w, fmaf(w1, v1.w, acc.w));
    }
    if (k < end) {
        int s0 = g_csr[k];
        float4 v0 = *reinterpret_cast<const float4*>(g_xl + (size_t)s0 * OUT_CH + lane * 4);
        float sc0 = a.x * lrelu(v0.x + xr4.x) + a.y * lrelu(v0.y + xr4.y)
                  + a.z * lrelu(v0.z + xr4.z) + a.w * lrelu(v0.w + xr4.w);
        sc0 += __shfl_xor_sync(0xFFFFFFFFu, sc0, 1);
        sc0 += __shfl_xor_sync(0xFFFFFFFFu, sc0, 2);
        sc0 += __shfl_xor_sync(0xFFFFFFFFu, sc0, 4);
        float w0 = __expf(sc0);
        denom += w0;
        acc.x = fmaf(w0, v0.x, acc.x);
        acc.y = fmaf(w0, v0.y, acc.y);
        acc.z = fmaf(w0, v0.z, acc.z);
        acc.w = fmaf(w0, v0.w, acc.w);
    }

    float inv = __frcp_rn(denom);
    float4 b = *reinterpret_cast<const float4*>(bias + lane * 4);
    float4 v;
    v.x = fmaf(acc.x, inv, b.x);
    v.y = fmaf(acc.y, inv, b.y);
    v.z = fmaf(acc.z, inv, b.z);
    v.w = fmaf(acc.w, inv, b.w);

    v.x = v.x / (1.f + __expf(-v.x));
    v.y = v.y / (1.f + __expf(-v.y));
    v.z = v.z / (1.f + __expf(-v.z));
    v.w = v.w / (1.f + __expf(-v.w));

    float sum = v.x + v.y + v.z + v.w;
    float sq  = v.x * v.x + v.y * v.y + v.z * v.z + v.w * v.w;
    #pragma unroll
    for (int off = 16; off; off >>= 1) {
        sum += __shfl_xor_sync(0xFFFFFFFFu, sum, off);
        sq  += __shfl_xor_sync(0xFFFFFFFFu, sq,  off);
    }
    float mu   = sum * (1.f / OUT_CH);
    float var  = sq * (1.f / OUT_CH) - mu * mu;
    float rstd = rsqrtf(var + LN_EPS);

    float4 g  = *reinterpret_cast<const float4*>(gamma + lane * 4);
    float4 be = *reinterpret_cast<const float4*>(beta  + lane * 4);
    float4 r;
    r.x = (v.x - mu) * rstd * g.x + be.x;
    r.y = (v.y - mu) * rstd * g.y + be.y;
    r.z = (v.z - mu) * rstd * g.z + be.z;
    r.w = (v.w - mu) * rstd * g.w + be.w;
    *reinterpret_cast<float4*>(out + (size_t)warp * OUT_CH + lane * 4) = r;
}

// ---------------- launcher ------------------------------------------------------------
extern "C" void kernel_launch(void* const* d_in, const int* in_sizes, int n_in,
                              void* d_out, int out_size)
{
    const float* x    = (const float*)d_in[0];
    const int*   ei   = (const int*)  d_in[1];
    const float* Wl   = (const float*)d_in[2];
    const float* bl   = (const float*)d_in[3];
    const float* Wr   = (const float*)d_in[4];
    const float* br   = (const float*)d_in[5];
    const float* att  = (const float*)d_in[6];
    const float* bias = (const float*)d_in[7];
    const float* gam  = (const float*)d_in[8];
    const float* bet  = (const float*)d_in[9];
    float* out = (float*)d_out;

    // order keeps the GEMM at iteration-launch index 3 (ncu capture slot)
    k_wconv<<<(IN_CH * OUT_CH + 255) / 256, 256>>>(Wl, Wr);            // 0
    k_init<<<(N_NODES + 255) / 256, 256>>>();                          // 1
    k_hist<<<(N_EDGES + 255) / 256, 256>>>(ei);                        // 2
    k_gemm_mma<<<(N_NODES + 63) / 64, 512>>>(x, bl, br);               // 3
    k_scan<<<NTILES, SCAN_B>>>();                                      // 4
    k_fill<<<(NE_TOT + 255) / 256, 256>>>(ei);                         // 5
    k_aggregate<<<(N_NODES * 32 + 255) / 256, 256>>>(att, bias, gam, bet, out); // 6
}